// round 3
// baseline (speedup 1.0000x reference)
#include <cuda_runtime.h>
#include <math.h>

// Problem constants
#define Bv   64
#define Nv   197
#define Cv   768
#define Hv   12
#define HDv  64
#define Tv   209      // N + H
#define C3v  2304     // 3*C

// ---------------- scratch (static device globals; no allocation) ----------------
__device__ float g_htmean[Bv * Cv];                 // (B, H*HD) == (B*H, HD) rows
__device__ float g_htlin [Bv * Hv * Cv];            // (B, H, C)
__device__ float g_xc   [Bv * Tv * Cv];             // (B, T, C)
__device__ float g_qkv  [Bv * Tv * C3v];            // (B, T, 3, H, HD)
__device__ float g_att  [Bv * Tv * Cv];             // (B, T, C)
__device__ float g_proj [Bv * Tv * Cv];             // (B, T, C)

// ---------------- kernel 1: head-token mean over N ----------------
__global__ void htmean_kernel(const float* __restrict__ x, float* __restrict__ out) {
    int idx = blockIdx.x * blockDim.x + threadIdx.x;
    if (idx >= Bv * Cv) return;
    int b = idx / Cv, c = idx % Cv;
    const float* p = x + (size_t)b * Nv * Cv + c;
    float s = 0.f;
    #pragma unroll 4
    for (int n = 0; n < Nv; n++) s += p[(size_t)n * Cv];
    out[idx] = s * (1.0f / Nv);
}

// ---------------- generic SGEMM: C = A(MxK) * B(KxN) + bias ----------------
// 128x128 tile, BK=16, 256 threads, 8x8 per thread, double-buffered smem.
// N % 128 == 0, K % 16 == 0. M may be ragged (guarded).
#define BM 128
#define BN 128
#define BK 16

__global__ __launch_bounds__(256, 2) void sgemm_bias(
    const float* __restrict__ A, const float* __restrict__ Bm,
    const float* __restrict__ bias, float* __restrict__ Cm,
    int M, int N, int K)
{
    __shared__ float As[2][BK][BM];   // stored transposed: As[buf][k][m]
    __shared__ float Bs[2][BK][BN];

    const int tid = threadIdx.x;
    const int bn = blockIdx.x, bm = blockIdx.y;
    const int row0 = bm * BM, col0 = bn * BN;

    const int tx = tid & 15;       // 0..15 -> N
    const int ty = tid >> 4;       // 0..15 -> M

    // A-load mapping: 128x16 tile, float4 along K. 512 float4 / 256 thr = 2 each.
    const int a_m  = tid >> 2;          // 0..63 (+64)
    const int a_k  = (tid & 3) * 4;     // 0,4,8,12
    // B-load mapping: 16x128 tile, float4 along N. 512 float4 / 256 thr = 2 each.
    const int b_k  = tid >> 5;          // 0..7 (+8)
    const int b_n  = (tid & 31) * 4;

    const int gr0 = row0 + a_m;
    const int gr1 = row0 + a_m + 64;
    const float* Ap0 = A + (size_t)gr0 * K + a_k;
    const float* Ap1 = A + (size_t)gr1 * K + a_k;
    const float* Bp0 = Bm + (size_t)b_k * N + col0 + b_n;
    const float* Bp1 = Bm + (size_t)(b_k + 8) * N + col0 + b_n;
    const size_t bstep = (size_t)BK * N;

    // bias prefetch (hidden behind the whole main loop)
    float4 bia0 = *(const float4*)(bias + col0 + tx * 8);
    float4 bia1 = *(const float4*)(bias + col0 + tx * 8 + 4);

    float acc[8][8];
    #pragma unroll
    for (int i = 0; i < 8; i++)
        #pragma unroll
        for (int j = 0; j < 8; j++) acc[i][j] = 0.f;

    // ---- preload tile 0 into buffer 0 ----
    {
        float4 va0 = make_float4(0.f,0.f,0.f,0.f), va1 = va0;
        if (gr0 < M) va0 = *(const float4*)(Ap0);
        if (gr1 < M) va1 = *(const float4*)(Ap1);
        float4 vb0 = *(const float4*)(Bp0);
        float4 vb1 = *(const float4*)(Bp1);
        As[0][a_k+0][a_m]    = va0.x; As[0][a_k+1][a_m]    = va0.y;
        As[0][a_k+2][a_m]    = va0.z; As[0][a_k+3][a_m]    = va0.w;
        As[0][a_k+0][a_m+64] = va1.x; As[0][a_k+1][a_m+64] = va1.y;
        As[0][a_k+2][a_m+64] = va1.z; As[0][a_k+3][a_m+64] = va1.w;
        *(float4*)&Bs[0][b_k][b_n]     = vb0;
        *(float4*)&Bs[0][b_k + 8][b_n] = vb1;
    }
    __syncthreads();

    const int ksteps = K / BK;
    int cur = 0;
    for (int kt = 0; kt < ksteps; kt++) {
        float4 va0, va1, vb0, vb1;
        const bool has_next = (kt + 1 < ksteps);
        if (has_next) {
            // prefetch next tile into registers (overlaps with compute below)
            int koff = (kt + 1) * BK;
            va0 = make_float4(0.f,0.f,0.f,0.f); va1 = va0;
            if (gr0 < M) va0 = *(const float4*)(Ap0 + koff);
            if (gr1 < M) va1 = *(const float4*)(Ap1 + koff);
            vb0 = *(const float4*)(Bp0 + (size_t)(kt + 1) * bstep);
            vb1 = *(const float4*)(Bp1 + (size_t)(kt + 1) * bstep);
        }

        // compute on current buffer
        #pragma unroll
        for (int k = 0; k < BK; k++) {
            float4 a01 = *(const float4*)&As[cur][k][ty * 8];
            float4 a23 = *(const float4*)&As[cur][k][ty * 8 + 4];
            float4 b01 = *(const float4*)&Bs[cur][k][tx * 8];
            float4 b23 = *(const float4*)&Bs[cur][k][tx * 8 + 4];
            float a[8] = {a01.x, a01.y, a01.z, a01.w, a23.x, a23.y, a23.z, a23.w};
            float b[8] = {b01.x, b01.y, b01.z, b01.w, b23.x, b23.y, b23.z, b23.w};
            #pragma unroll
            for (int i = 0; i < 8; i++)
                #pragma unroll
                for (int j = 0; j < 8; j++)
                    acc[i][j] += a[i] * b[j];
        }

        if (has_next) {
            int nxt = cur ^ 1;
            As[nxt][a_k+0][a_m]    = va0.x; As[nxt][a_k+1][a_m]    = va0.y;
            As[nxt][a_k+2][a_m]    = va0.z; As[nxt][a_k+3][a_m]    = va0.w;
            As[nxt][a_k+0][a_m+64] = va1.x; As[nxt][a_k+1][a_m+64] = va1.y;
            As[nxt][a_k+2][a_m+64] = va1.z; As[nxt][a_k+3][a_m+64] = va1.w;
            *(float4*)&Bs[nxt][b_k][b_n]     = vb0;
            *(float4*)&Bs[nxt][b_k + 8][b_n] = vb1;
            __syncthreads();
            cur = nxt;
        }
    }

    // epilogue with bias
    #pragma unroll
    for (int i = 0; i < 8; i++) {
        int r = row0 + ty * 8 + i;
        if (r >= M) break;
        float4 o0 = make_float4(acc[i][0] + bia0.x, acc[i][1] + bia0.y,
                                acc[i][2] + bia0.z, acc[i][3] + bia0.w);
        float4 o1 = make_float4(acc[i][4] + bia1.x, acc[i][5] + bia1.y,
                                acc[i][6] + bia1.z, acc[i][7] + bia1.w);
        float* cp = Cm + (size_t)r * N + col0 + tx * 8;
        *(float4*)cp       = o0;
        *(float4*)(cp + 4) = o1;
    }
}

// ---------------- kernel 3: group LayerNorm(HD) + exact GELU + pos_embed ----------------
// writes directly into xc rows [N, T)
__global__ void ln_gelu_pos_kernel(const float* __restrict__ htlin,
                                   const float* __restrict__ lng,
                                   const float* __restrict__ lnb,
                                   const float* __restrict__ pos,
                                   float* __restrict__ xc)
{
    int gidx = blockIdx.x;                 // b*H*H + h*H + g
    int b = gidx / (Hv * Hv);
    int rem = gidx % (Hv * Hv);
    int h = rem / Hv, g = rem % Hv;
    int t = threadIdx.x;                   // 0..63

    float v = htlin[((size_t)(b * Hv + h)) * Cv + g * HDv + t];
    float s = v, s2 = v * v;
    #pragma unroll
    for (int off = 16; off; off >>= 1) {
        s  += __shfl_xor_sync(0xffffffffu, s,  off);
        s2 += __shfl_xor_sync(0xffffffffu, s2, off);
    }
    __shared__ float sh[4];
    int w = t >> 5, lane = t & 31;
    if (lane == 0) { sh[w] = s; sh[2 + w] = s2; }
    __syncthreads();
    float tot  = sh[0] + sh[1];
    float tot2 = sh[2] + sh[3];
    float mu  = tot * (1.f / HDv);
    float var = tot2 * (1.f / HDv) - mu * mu;
    float xn = (v - mu) * rsqrtf(var + 1e-5f) * lng[t] + lnb[t];
    float ge = 0.5f * xn * (1.f + erff(xn * 0.70710678118654752f));
    ge += pos[h * Cv + g * HDv + t];
    xc[((size_t)b * Tv + Nv + h) * Cv + g * HDv + t] = ge;
}

// ---------------- kernel 5: attention, one block per (b,h) ----------------
// smem: sKT[64][256] (K transposed, zero padded), sV[209][64], sP[8][224], sQ[8][64]
#define ATT_KT_STRIDE 256
#define ATT_P_STRIDE  224
#define ATT_SMEM_FLOATS (64*ATT_KT_STRIDE + Tv*HDv + 8*ATT_P_STRIDE + 8*HDv)

__global__ __launch_bounds__(256) void attn_kernel(const float* __restrict__ qkv,
                                                   float* __restrict__ attout)
{
    extern __shared__ float sm[];
    float* sKT = sm;                               // [64][256]
    float* sV  = sKT + 64 * ATT_KT_STRIDE;         // [209][64]
    float* sP  = sV + Tv * HDv;                    // [8][224]
    float* sQ  = sP + 8 * ATT_P_STRIDE;            // [8][64]

    int bh = blockIdx.x;
    int b = bh / Hv, h = bh % Hv;
    int tid = threadIdx.x;
    int w = tid >> 5, lane = tid & 31;
    const size_t base = (size_t)b * Tv * C3v + h * HDv;

    // zero padded KT region
    for (int i = tid; i < 64 * ATT_KT_STRIDE; i += 256) sKT[i] = 0.f;
    __syncthreads();
    // load K (transposed) and V
    for (int i = tid; i < Tv * HDv; i += 256) {
        int t = i >> 6, d = i & 63;
        sKT[d * ATT_KT_STRIDE + t] = qkv[base + (size_t)t * C3v + 768 + d];
        sV[i]                      = qkv[base + (size_t)t * C3v + 1536 + d];
    }
    __syncthreads();

    for (int r = w; r < Tv; r += 8) {
        // load this row's q into per-warp smem
        sQ[w * 64 + lane]      = qkv[base + (size_t)r * C3v + lane];
        sQ[w * 64 + lane + 32] = qkv[base + (size_t)r * C3v + lane + 32];
        __syncwarp();

        float acc[8];
        #pragma unroll
        for (int i = 0; i < 8; i++) acc[i] = 0.f;

        #pragma unroll 8
        for (int d = 0; d < 64; d++) {
            float qd = sQ[w * 64 + d];
            float4 k0 = *(const float4*)&sKT[d * ATT_KT_STRIDE + lane * 4];
            float4 k1 = *(const float4*)&sKT[d * ATT_KT_STRIDE + 128 + lane * 4];
            acc[0] += qd * k0.x; acc[1] += qd * k0.y;
            acc[2] += qd * k0.z; acc[3] += qd * k0.w;
            acc[4] += qd * k1.x; acc[5] += qd * k1.y;
            acc[6] += qd * k1.z; acc[7] += qd * k1.w;
        }

        // scale, mask, softmax over j (lane covers j = lane*4+i and 128+lane*4+i)
        float m = -INFINITY;
        #pragma unroll
        for (int i = 0; i < 8; i++) {
            int j = (i < 4) ? (lane * 4 + i) : (128 + lane * 4 + (i - 4));
            acc[i] = (j < Tv) ? acc[i] * 0.125f : -INFINITY;
            m = fmaxf(m, acc[i]);
        }
        #pragma unroll
        for (int off = 16; off; off >>= 1)
            m = fmaxf(m, __shfl_xor_sync(0xffffffffu, m, off));
        float ssum = 0.f;
        #pragma unroll
        for (int i = 0; i < 8; i++) { acc[i] = __expf(acc[i] - m); ssum += acc[i]; }
        #pragma unroll
        for (int off = 16; off; off >>= 1)
            ssum += __shfl_xor_sync(0xffffffffu, ssum, off);
        float inv = 1.f / ssum;
        #pragma unroll
        for (int i = 0; i < 8; i++) {
            int j = (i < 4) ? (lane * 4 + i) : (128 + lane * 4 + (i - 4));
            if (j < Tv) sP[w * ATT_P_STRIDE + j] = acc[i] * inv;
        }
        __syncwarp();

        // O = P @ V : lane covers d = lane*2, lane*2+1
        float o0 = 0.f, o1 = 0.f;
        #pragma unroll 4
        for (int j = 0; j < Tv; j++) {
            float pj = sP[w * ATT_P_STRIDE + j];
            float2 vv = *(const float2*)&sV[j * 64 + lane * 2];
            o0 += pj * vv.x;
            o1 += pj * vv.y;
        }
        float* op = attout + ((size_t)b * Tv + r) * Cv + h * HDv + lane * 2;
        op[0] = o0; op[1] = o1;
        __syncwarp();
    }
}

// ---------------- kernel 7: cls merge + copy ----------------
__global__ void final_kernel(const float* __restrict__ pr, float* __restrict__ out) {
    int idx = blockIdx.x * blockDim.x + threadIdx.x;
    const int total = Bv * Nv * Cv;
    if (idx >= total) return;
    int c = idx % Cv;
    int t = (idx / Cv) % Nv;
    int b = idx / (Nv * Cv);
    float v = pr[((size_t)b * Tv + t) * Cv + c];
    if (t == 0) {
        float s = 0.f;
        #pragma unroll
        for (int hh = 0; hh < Hv; hh++)
            s += pr[((size_t)b * Tv + Nv + hh) * Cv + c];
        v += s * (1.f / Hv);
    }
    out[idx] = v;
}

// ---------------- launcher ----------------
extern "C" void kernel_launch(void* const* d_in, const int* in_sizes, int n_in,
                              void* d_out, int out_size)
{
    const float* x      = (const float*)d_in[0];
    const float* qkv_w  = (const float*)d_in[1];
    const float* qkv_b  = (const float*)d_in[2];
    const float* proj_w = (const float*)d_in[3];
    const float* proj_b = (const float*)d_in[4];
    const float* ht_w   = (const float*)d_in[5];
    const float* ht_b   = (const float*)d_in[6];
    const float* ln_g   = (const float*)d_in[7];
    const float* ln_b   = (const float*)d_in[8];
    const float* pos    = (const float*)d_in[9];
    float* out          = (float*)d_out;

    float *p_htmean, *p_htlin, *p_xc, *p_qkv, *p_att, *p_proj;
    cudaGetSymbolAddress((void**)&p_htmean, g_htmean);
    cudaGetSymbolAddress((void**)&p_htlin,  g_htlin);
    cudaGetSymbolAddress((void**)&p_xc,     g_xc);
    cudaGetSymbolAddress((void**)&p_qkv,    g_qkv);
    cudaGetSymbolAddress((void**)&p_att,    g_att);
    cudaGetSymbolAddress((void**)&p_proj,   g_proj);

    // copy x into the first N rows of each batch of xc (strided 2D D2D copy)
    cudaMemcpy2DAsync(p_xc, (size_t)Tv * Cv * sizeof(float),
                      x,    (size_t)Nv * Cv * sizeof(float),
                      (size_t)Nv * Cv * sizeof(float), Bv,
                      cudaMemcpyDeviceToDevice, 0);

    // 1) head-token mean over N
    {
        int total = Bv * Cv;
        htmean_kernel<<<(total + 255) / 256, 256>>>(x, p_htmean);
    }

    // 2) ht linear: (B*H, HD) @ (HD, C) + ht_b  -> (B, H, C)
    {
        dim3 grid(Cv / BN, (Bv * Hv + BM - 1) / BM);
        sgemm_bias<<<grid, 256>>>(p_htmean, ht_w, ht_b, p_htlin, Bv * Hv, Cv, HDv);
    }

    // 3) LN + GELU + pos_embed -> xc rows [N, T)
    ln_gelu_pos_kernel<<<Bv * Hv * Hv, 64>>>(p_htlin, ln_g, ln_b, pos, p_xc);

    // 4) QKV GEMM: (B*T, C) @ (C, 3C) + qkv_b
    {
        dim3 grid(C3v / BN, (Bv * Tv + BM - 1) / BM);
        sgemm_bias<<<grid, 256>>>(p_xc, qkv_w, qkv_b, p_qkv, Bv * Tv, C3v, Cv);
    }

    // 5) attention per (b, h)
    {
        size_t smem = ATT_SMEM_FLOATS * sizeof(float);
        cudaFuncSetAttribute(attn_kernel, cudaFuncAttributeMaxDynamicSharedMemorySize, (int)smem);
        attn_kernel<<<Bv * Hv, 256, smem>>>(p_qkv, p_att);
    }

    // 6) proj GEMM: (B*T, C) @ (C, C) + proj_b
    {
        dim3 grid(Cv / BN, (Bv * Tv + BM - 1) / BM);
        sgemm_bias<<<grid, 256>>>(p_att, proj_w, proj_b, p_proj, Bv * Tv, Cv, Cv);
    }

    // 7) cls merge + output copy
    {
        int total = Bv * Nv * Cv;
        final_kernel<<<(total + 255) / 256, 256>>>(p_proj, out);
    }
}

// round 4
// speedup vs baseline: 1.7105x; 1.7105x over previous
#include <cuda_runtime.h>
#include <math.h>
#include <stdint.h>

// Problem constants
#define Bv   64
#define Nv   197
#define Cv   768
#define Hv   12
#define HDv  64
#define Tv   209      // N + H
#define C3v  2304     // 3*C

// ---------------- scratch (static device globals; no allocation) ----------------
__device__ float g_htmean[Bv * Cv];
__device__ float g_htlin [Bv * Hv * Cv];
__device__ float g_xc   [Bv * Tv * Cv];
__device__ float g_qkv  [Bv * Tv * C3v];
__device__ float g_att  [Bv * Tv * Cv];
__device__ float g_proj [Bv * Tv * Cv];

// ---------------- kernel 1: head-token mean over N ----------------
__global__ void htmean_kernel(const float* __restrict__ x, float* __restrict__ out) {
    int idx = blockIdx.x * blockDim.x + threadIdx.x;
    if (idx >= Bv * Cv) return;
    int b = idx / Cv, c = idx % Cv;
    const float* p = x + (size_t)b * Nv * Cv + c;
    float s = 0.f;
    #pragma unroll 4
    for (int n = 0; n < Nv; n++) s += p[(size_t)n * Cv];
    out[idx] = s * (1.0f / Nv);
}

// ---------------- tf32 helpers ----------------
__device__ __forceinline__ uint32_t f2tf32(float x) {
    uint32_t r;
    asm("cvt.rna.tf32.f32 %0, %1;" : "=r"(r) : "f"(x));
    return r;
}
__device__ __forceinline__ float4 cvt4(float4 v) {
    float4 o;
    o.x = __uint_as_float(f2tf32(v.x));
    o.y = __uint_as_float(f2tf32(v.y));
    o.z = __uint_as_float(f2tf32(v.z));
    o.w = __uint_as_float(f2tf32(v.w));
    return o;
}
__device__ __forceinline__ void mma_tf32(float c[4], const uint32_t a[4], const uint32_t b[2]) {
    asm volatile(
        "mma.sync.aligned.m16n8k8.row.col.f32.tf32.tf32.f32 "
        "{%0,%1,%2,%3}, {%4,%5,%6,%7}, {%8,%9}, {%0,%1,%2,%3};"
        : "+f"(c[0]), "+f"(c[1]), "+f"(c[2]), "+f"(c[3])
        : "r"(a[0]), "r"(a[1]), "r"(a[2]), "r"(a[3]), "r"(b[0]), "r"(b[1]));
}

// ---------------- tf32 tensor-core GEMM: C = A(MxK) * B(KxN) + bias ----------------
// 128x128 tile, BK=16, 256 threads (8 warps, 2x4), m16n8k8 mma, double-buffered.
// N % 128 == 0, K % 16 == 0, M ragged (guarded). Inputs rounded to tf32 (rna).
#define BM 128
#define BN 128
#define BKT 16
#define AS_STRIDE 20    // floats per A row  (bank-clean: g*20+tg covers 32 banks)
#define BS_STRIDE 136   // floats per B row  (bank-clean: tg*8 + g disjoint)

__global__ __launch_bounds__(256, 2) void tgemm_bias(
    const float* __restrict__ A, const float* __restrict__ Bm,
    const float* __restrict__ bias, float* __restrict__ Cm,
    int M, int N, int K)
{
    __shared__ float As[2][BM][AS_STRIDE];   // [m][k]
    __shared__ float Bs[2][BKT][BS_STRIDE];  // [k][n]

    const int tid = threadIdx.x;
    const int bn = blockIdx.x, bm = blockIdx.y;
    const int row0 = bm * BM, col0 = bn * BN;

    const int wid = tid >> 5, lane = tid & 31;
    const int wm = wid & 1, wn = wid >> 1;   // warp tile: 64 rows x 32 cols
    const int g  = lane >> 2, tg = lane & 3;

    // global-load mapping (same as validated fp32 version)
    const int a_m = tid >> 2;            // 0..63 (+64)
    const int a_k = (tid & 3) * 4;       // 0,4,8,12
    const int b_k = tid >> 5;            // 0..7 (+8)
    const int b_n = (tid & 31) * 4;

    const int gr0 = row0 + a_m;
    const int gr1 = row0 + a_m + 64;
    const float* Ap0 = A + (size_t)gr0 * K + a_k;
    const float* Ap1 = A + (size_t)gr1 * K + a_k;
    const float* Bp0 = Bm + (size_t)b_k * N + col0 + b_n;
    const float* Bp1 = Bm + (size_t)(b_k + 8) * N + col0 + b_n;
    const size_t bstep = (size_t)BKT * N;

    float acc[4][4][4];   // [mi][ni][frag]
    #pragma unroll
    for (int mi = 0; mi < 4; mi++)
        #pragma unroll
        for (int ni = 0; ni < 4; ni++)
            #pragma unroll
            for (int f = 0; f < 4; f++) acc[mi][ni][f] = 0.f;

    // ---- preload tile 0 ----
    {
        float4 va0 = make_float4(0.f,0.f,0.f,0.f), va1 = va0;
        if (gr0 < M) va0 = *(const float4*)(Ap0);
        if (gr1 < M) va1 = *(const float4*)(Ap1);
        float4 vb0 = *(const float4*)(Bp0);
        float4 vb1 = *(const float4*)(Bp1);
        *(float4*)&As[0][a_m][a_k]      = cvt4(va0);
        *(float4*)&As[0][a_m + 64][a_k] = cvt4(va1);
        *(float4*)&Bs[0][b_k][b_n]      = cvt4(vb0);
        *(float4*)&Bs[0][b_k + 8][b_n]  = cvt4(vb1);
    }
    __syncthreads();

    const int ksteps = K / BKT;
    int cur = 0;
    for (int kt = 0; kt < ksteps; kt++) {
        float4 va0, va1, vb0, vb1;
        const bool has_next = (kt + 1 < ksteps);
        if (has_next) {
            int koff = (kt + 1) * BKT;
            va0 = make_float4(0.f,0.f,0.f,0.f); va1 = va0;
            if (gr0 < M) va0 = *(const float4*)(Ap0 + koff);
            if (gr1 < M) va1 = *(const float4*)(Ap1 + koff);
            vb0 = *(const float4*)(Bp0 + (size_t)(kt + 1) * bstep);
            vb1 = *(const float4*)(Bp1 + (size_t)(kt + 1) * bstep);
        }

        // ---- compute on current buffer: 2 k8-steps ----
        #pragma unroll
        for (int kk = 0; kk < BKT; kk += 8) {
            uint32_t af[4][4], bf[4][2];
            #pragma unroll
            for (int mi = 0; mi < 4; mi++) {
                int m = wm * 64 + mi * 16;
                af[mi][0] = __float_as_uint(As[cur][m + g     ][kk + tg    ]);
                af[mi][1] = __float_as_uint(As[cur][m + g + 8 ][kk + tg    ]);
                af[mi][2] = __float_as_uint(As[cur][m + g     ][kk + tg + 4]);
                af[mi][3] = __float_as_uint(As[cur][m + g + 8 ][kk + tg + 4]);
            }
            #pragma unroll
            for (int ni = 0; ni < 4; ni++) {
                int n = wn * 32 + ni * 8;
                bf[ni][0] = __float_as_uint(Bs[cur][kk + tg    ][n + g]);
                bf[ni][1] = __float_as_uint(Bs[cur][kk + tg + 4][n + g]);
            }
            #pragma unroll
            for (int mi = 0; mi < 4; mi++)
                #pragma unroll
                for (int ni = 0; ni < 4; ni++)
                    mma_tf32(acc[mi][ni], af[mi], bf[ni]);
        }

        if (has_next) {
            int nxt = cur ^ 1;
            *(float4*)&As[nxt][a_m][a_k]      = cvt4(va0);
            *(float4*)&As[nxt][a_m + 64][a_k] = cvt4(va1);
            *(float4*)&Bs[nxt][b_k][b_n]      = cvt4(vb0);
            *(float4*)&Bs[nxt][b_k + 8][b_n]  = cvt4(vb1);
            __syncthreads();
            cur = nxt;
        }
    }

    // ---- epilogue: c0=D[g][2tg] c1=D[g][2tg+1] c2=D[g+8][2tg] c3=D[g+8][2tg+1]
    #pragma unroll
    for (int ni = 0; ni < 4; ni++) {
        int c = col0 + wn * 32 + ni * 8 + 2 * tg;
        float2 bi = *(const float2*)(bias + c);
        #pragma unroll
        for (int mi = 0; mi < 4; mi++) {
            int r0 = row0 + wm * 64 + mi * 16 + g;
            int r1 = r0 + 8;
            if (r0 < M) {
                float2 o = make_float2(acc[mi][ni][0] + bi.x, acc[mi][ni][1] + bi.y);
                *(float2*)(Cm + (size_t)r0 * N + c) = o;
            }
            if (r1 < M) {
                float2 o = make_float2(acc[mi][ni][2] + bi.x, acc[mi][ni][3] + bi.y);
                *(float2*)(Cm + (size_t)r1 * N + c) = o;
            }
        }
    }
}

// ---------------- kernel 3: group LayerNorm(HD) + exact GELU + pos_embed ----------------
__global__ void ln_gelu_pos_kernel(const float* __restrict__ htlin,
                                   const float* __restrict__ lng,
                                   const float* __restrict__ lnb,
                                   const float* __restrict__ pos,
                                   float* __restrict__ xc)
{
    int gidx = blockIdx.x;                 // b*H*H + h*H + g
    int b = gidx / (Hv * Hv);
    int rem = gidx % (Hv * Hv);
    int h = rem / Hv, g = rem % Hv;
    int t = threadIdx.x;                   // 0..63

    float v = htlin[((size_t)(b * Hv + h)) * Cv + g * HDv + t];
    float s = v, s2 = v * v;
    #pragma unroll
    for (int off = 16; off; off >>= 1) {
        s  += __shfl_xor_sync(0xffffffffu, s,  off);
        s2 += __shfl_xor_sync(0xffffffffu, s2, off);
    }
    __shared__ float sh[4];
    int w = t >> 5, lane = t & 31;
    if (lane == 0) { sh[w] = s; sh[2 + w] = s2; }
    __syncthreads();
    float tot  = sh[0] + sh[1];
    float tot2 = sh[2] + sh[3];
    float mu  = tot * (1.f / HDv);
    float var = tot2 * (1.f / HDv) - mu * mu;
    float xn = (v - mu) * rsqrtf(var + 1e-5f) * lng[t] + lnb[t];
    float ge = 0.5f * xn * (1.f + erff(xn * 0.70710678118654752f));
    ge += pos[h * Cv + g * HDv + t];
    xc[((size_t)b * Tv + Nv + h) * Cv + g * HDv + t] = ge;
}

// ---------------- kernel 5: attention, one block per (b,h) ----------------
#define ATT_KT_STRIDE 256
#define ATT_P_STRIDE  224
#define ATT_SMEM_FLOATS (64*ATT_KT_STRIDE + Tv*HDv + 8*ATT_P_STRIDE + 8*HDv)

__global__ __launch_bounds__(256) void attn_kernel(const float* __restrict__ qkv,
                                                   float* __restrict__ attout)
{
    extern __shared__ float sm[];
    float* sKT = sm;                               // [64][256]
    float* sV  = sKT + 64 * ATT_KT_STRIDE;         // [209][64]
    float* sP  = sV + Tv * HDv;                    // [8][224]
    float* sQ  = sP + 8 * ATT_P_STRIDE;            // [8][64]

    int bh = blockIdx.x;
    int b = bh / Hv, h = bh % Hv;
    int tid = threadIdx.x;
    int w = tid >> 5, lane = tid & 31;
    const size_t base = (size_t)b * Tv * C3v + h * HDv;

    for (int i = tid; i < 64 * ATT_KT_STRIDE; i += 256) sKT[i] = 0.f;
    __syncthreads();
    for (int i = tid; i < Tv * HDv; i += 256) {
        int t = i >> 6, d = i & 63;
        sKT[d * ATT_KT_STRIDE + t] = qkv[base + (size_t)t * C3v + 768 + d];
        sV[i]                      = qkv[base + (size_t)t * C3v + 1536 + d];
    }
    __syncthreads();

    for (int r = w; r < Tv; r += 8) {
        sQ[w * 64 + lane]      = qkv[base + (size_t)r * C3v + lane];
        sQ[w * 64 + lane + 32] = qkv[base + (size_t)r * C3v + lane + 32];
        __syncwarp();

        float acc[8];
        #pragma unroll
        for (int i = 0; i < 8; i++) acc[i] = 0.f;

        #pragma unroll 8
        for (int d = 0; d < 64; d++) {
            float qd = sQ[w * 64 + d];
            float4 k0 = *(const float4*)&sKT[d * ATT_KT_STRIDE + lane * 4];
            float4 k1 = *(const float4*)&sKT[d * ATT_KT_STRIDE + 128 + lane * 4];
            acc[0] += qd * k0.x; acc[1] += qd * k0.y;
            acc[2] += qd * k0.z; acc[3] += qd * k0.w;
            acc[4] += qd * k1.x; acc[5] += qd * k1.y;
            acc[6] += qd * k1.z; acc[7] += qd * k1.w;
        }

        float m = -INFINITY;
        #pragma unroll
        for (int i = 0; i < 8; i++) {
            int j = (i < 4) ? (lane * 4 + i) : (128 + lane * 4 + (i - 4));
            acc[i] = (j < Tv) ? acc[i] * 0.125f : -INFINITY;
            m = fmaxf(m, acc[i]);
        }
        #pragma unroll
        for (int off = 16; off; off >>= 1)
            m = fmaxf(m, __shfl_xor_sync(0xffffffffu, m, off));
        float ssum = 0.f;
        #pragma unroll
        for (int i = 0; i < 8; i++) { acc[i] = __expf(acc[i] - m); ssum += acc[i]; }
        #pragma unroll
        for (int off = 16; off; off >>= 1)
            ssum += __shfl_xor_sync(0xffffffffu, ssum, off);
        float inv = 1.f / ssum;
        #pragma unroll
        for (int i = 0; i < 8; i++) {
            int j = (i < 4) ? (lane * 4 + i) : (128 + lane * 4 + (i - 4));
            if (j < Tv) sP[w * ATT_P_STRIDE + j] = acc[i] * inv;
        }
        __syncwarp();

        float o0 = 0.f, o1 = 0.f;
        #pragma unroll 4
        for (int j = 0; j < Tv; j++) {
            float pj = sP[w * ATT_P_STRIDE + j];
            float2 vv = *(const float2*)&sV[j * 64 + lane * 2];
            o0 += pj * vv.x;
            o1 += pj * vv.y;
        }
        float* op = attout + ((size_t)b * Tv + r) * Cv + h * HDv + lane * 2;
        op[0] = o0; op[1] = o1;
        __syncwarp();
    }
}

// ---------------- kernel 7: cls merge + copy ----------------
__global__ void final_kernel(const float* __restrict__ pr, float* __restrict__ out) {
    int idx = blockIdx.x * blockDim.x + threadIdx.x;
    const int total = Bv * Nv * Cv;
    if (idx >= total) return;
    int c = idx % Cv;
    int t = (idx / Cv) % Nv;
    int b = idx / (Nv * Cv);
    float v = pr[((size_t)b * Tv + t) * Cv + c];
    if (t == 0) {
        float s = 0.f;
        #pragma unroll
        for (int hh = 0; hh < Hv; hh++)
            s += pr[((size_t)b * Tv + Nv + hh) * Cv + c];
        v += s * (1.f / Hv);
    }
    out[idx] = v;
}

// ---------------- launcher ----------------
extern "C" void kernel_launch(void* const* d_in, const int* in_sizes, int n_in,
                              void* d_out, int out_size)
{
    const float* x      = (const float*)d_in[0];
    const float* qkv_w  = (const float*)d_in[1];
    const float* qkv_b  = (const float*)d_in[2];
    const float* proj_w = (const float*)d_in[3];
    const float* proj_b = (const float*)d_in[4];
    const float* ht_w   = (const float*)d_in[5];
    const float* ht_b   = (const float*)d_in[6];
    const float* ln_g   = (const float*)d_in[7];
    const float* ln_b   = (const float*)d_in[8];
    const float* pos    = (const float*)d_in[9];
    float* out          = (float*)d_out;

    float *p_htmean, *p_htlin, *p_xc, *p_qkv, *p_att, *p_proj;
    cudaGetSymbolAddress((void**)&p_htmean, g_htmean);
    cudaGetSymbolAddress((void**)&p_htlin,  g_htlin);
    cudaGetSymbolAddress((void**)&p_xc,     g_xc);
    cudaGetSymbolAddress((void**)&p_qkv,    g_qkv);
    cudaGetSymbolAddress((void**)&p_att,    g_att);
    cudaGetSymbolAddress((void**)&p_proj,   g_proj);

    // copy x into the first N rows of each batch of xc
    cudaMemcpy2DAsync(p_xc, (size_t)Tv * Cv * sizeof(float),
                      x,    (size_t)Nv * Cv * sizeof(float),
                      (size_t)Nv * Cv * sizeof(float), Bv,
                      cudaMemcpyDeviceToDevice, 0);

    // 1) head-token mean over N
    {
        int total = Bv * Cv;
        htmean_kernel<<<(total + 255) / 256, 256>>>(x, p_htmean);
    }

    // 2) ht linear: (B*H, HD) @ (HD, C) + ht_b
    {
        dim3 grid(Cv / BN, (Bv * Hv + BM - 1) / BM);
        tgemm_bias<<<grid, 256>>>(p_htmean, ht_w, ht_b, p_htlin, Bv * Hv, Cv, HDv);
    }

    // 3) LN + GELU + pos_embed -> xc rows [N, T)
    ln_gelu_pos_kernel<<<Bv * Hv * Hv, 64>>>(p_htlin, ln_g, ln_b, pos, p_xc);

    // 4) QKV GEMM: (B*T, C) @ (C, 3C) + qkv_b
    {
        dim3 grid(C3v / BN, (Bv * Tv + BM - 1) / BM);
        tgemm_bias<<<grid, 256>>>(p_xc, qkv_w, qkv_b, p_qkv, Bv * Tv, C3v, Cv);
    }

    // 5) attention per (b, h)
    {
        size_t smem = ATT_SMEM_FLOATS * sizeof(float);
        cudaFuncSetAttribute(attn_kernel, cudaFuncAttributeMaxDynamicSharedMemorySize, (int)smem);
        attn_kernel<<<Bv * Hv, 256, smem>>>(p_qkv, p_att);
    }

    // 6) proj GEMM: (B*T, C) @ (C, C) + proj_b
    {
        dim3 grid(Cv / BN, (Bv * Tv + BM - 1) / BM);
        tgemm_bias<<<grid, 256>>>(p_att, proj_w, proj_b, p_proj, Bv * Tv, Cv, Cv);
    }

    // 7) cls merge + output copy
    {
        int total = Bv * Nv * Cv;
        final_kernel<<<(total + 255) / 256, 256>>>(p_proj, out);
    }
}

// round 5
// speedup vs baseline: 1.8405x; 1.0760x over previous
#include <cuda_runtime.h>
#include <math.h>
#include <stdint.h>

// Problem constants
#define Bv   64
#define Nv   197
#define Cv   768
#define Hv   12
#define HDv  64
#define Tv   209      // N + H
#define C3v  2304     // 3*C

// ---------------- scratch (static device globals; no allocation) ----------------
__device__ float g_htmean[Bv * Cv];
__device__ float g_htlin [Bv * Hv * Cv];
__device__ float g_xc   [Bv * Tv * Cv];
__device__ float g_qkv  [Bv * Tv * C3v];
__device__ float g_att  [Bv * Tv * Cv];
__device__ float g_proj [Bv * Tv * Cv];

// ---------------- kernel 1: head-token mean over N ----------------
__global__ void htmean_kernel(const float* __restrict__ x, float* __restrict__ out) {
    int idx = blockIdx.x * blockDim.x + threadIdx.x;
    if (idx >= Bv * Cv) return;
    int b = idx / Cv, c = idx % Cv;
    const float* p = x + (size_t)b * Nv * Cv + c;
    float s = 0.f;
    #pragma unroll 4
    for (int n = 0; n < Nv; n++) s += p[(size_t)n * Cv];
    out[idx] = s * (1.0f / Nv);
}

// ---------------- tf32 / ldmatrix helpers ----------------
__device__ __forceinline__ uint32_t f2tf32(float x) {
    uint32_t r;
    asm("cvt.rna.tf32.f32 %0, %1;" : "=r"(r) : "f"(x));
    return r;
}
__device__ __forceinline__ float4 cvt4(float4 v) {
    float4 o;
    o.x = __uint_as_float(f2tf32(v.x));
    o.y = __uint_as_float(f2tf32(v.y));
    o.z = __uint_as_float(f2tf32(v.z));
    o.w = __uint_as_float(f2tf32(v.w));
    return o;
}
__device__ __forceinline__ void mma_tf32(float c[4], const uint32_t a[4], const uint32_t b[2]) {
    asm volatile(
        "mma.sync.aligned.m16n8k8.row.col.f32.tf32.tf32.f32 "
        "{%0,%1,%2,%3}, {%4,%5,%6,%7}, {%8,%9}, {%0,%1,%2,%3};"
        : "+f"(c[0]), "+f"(c[1]), "+f"(c[2]), "+f"(c[3])
        : "r"(a[0]), "r"(a[1]), "r"(a[2]), "r"(a[3]), "r"(b[0]), "r"(b[1]));
}
__device__ __forceinline__ void ldsm_x4(uint32_t addr, uint32_t& r0, uint32_t& r1,
                                        uint32_t& r2, uint32_t& r3) {
    asm volatile("ldmatrix.sync.aligned.m8n8.x4.shared.b16 {%0,%1,%2,%3}, [%4];"
                 : "=r"(r0), "=r"(r1), "=r"(r2), "=r"(r3) : "r"(addr));
}
__device__ __forceinline__ void ldsm_x2(uint32_t addr, uint32_t& r0, uint32_t& r1) {
    asm volatile("ldmatrix.sync.aligned.m8n8.x2.shared.b16 {%0,%1}, [%2];"
                 : "=r"(r0), "=r"(r1) : "r"(addr));
}

// ---------------- tf32 tensor-core GEMM: C = A(MxK) * B(KxN) + bias ----------------
// 128x128 tile, BK=16, 256 threads (8 warps, 2x4), m16n8k8 mma, double-buffered,
// fragments via ldmatrix. Both A and B tiles stored [row][k] with stride 20.
#define BM 128
#define BN 128
#define BKT 16
#define TS 20   // k-stride in floats for both tiles (80 B rows: 16B-aligned, bank-clean)

__global__ __launch_bounds__(256, 2) void tgemm_bias(
    const float* __restrict__ A, const float* __restrict__ Bm,
    const float* __restrict__ bias, float* __restrict__ Cm,
    int M, int N, int K)
{
    __shared__ float As [2][BM][TS];   // [m][k]
    __shared__ float Bst[2][BN][TS];   // [n][k]  (B transposed)

    const int tid = threadIdx.x;
    const int bn = blockIdx.x, bm = blockIdx.y;
    const int row0 = bm * BM, col0 = bn * BN;

    const int wid = tid >> 5, lane = tid & 31;
    const int wm = wid & 1, wn = wid >> 1;   // warp tile: 64 rows x 32 cols
    const int g  = lane >> 2, tg = lane & 3;

    // A global-load mapping: 128x16 tile, float4 along K, 2 rows per thread.
    const int a_m = tid >> 2;            // 0..63 (+64)
    const int a_k = (tid & 3) * 4;       // 0,4,8,12
    // B global-load mapping: each thread owns one n-column, 8 k-values.
    const int b_n  = tid & 127;          // 0..127
    const int b_k0 = (tid >> 7) * 8;     // 0 or 8

    const int gr0 = row0 + a_m;
    const int gr1 = row0 + a_m + 64;
    const float* Ap0 = A + (size_t)gr0 * K + a_k;
    const float* Ap1 = A + (size_t)gr1 * K + a_k;
    const float* Bp  = Bm + (size_t)b_k0 * N + col0 + b_n;   // advance by kt*BKT*N

    // fragment smem addresses (ldmatrix)
    const int a_frow = lane & 15;
    const int a_fcol = (lane >> 4) << 2;           // 0 or 4 (+kk)
    const int b_frow = lane & 7;
    const int b_fcol = ((lane >> 3) & 1) << 2;     // 0 or 4 (+kk)

    float acc[4][4][4];
    #pragma unroll
    for (int mi = 0; mi < 4; mi++)
        #pragma unroll
        for (int ni = 0; ni < 4; ni++)
            #pragma unroll
            for (int f = 0; f < 4; f++) acc[mi][ni][f] = 0.f;

    // ---- preload tile 0 ----
    {
        float4 va0 = make_float4(0.f,0.f,0.f,0.f), va1 = va0;
        if (gr0 < M) va0 = *(const float4*)(Ap0);
        if (gr1 < M) va1 = *(const float4*)(Ap1);
        float rb[8];
        #pragma unroll
        for (int i = 0; i < 8; i++) rb[i] = Bp[(size_t)i * N];
        *(float4*)&As[0][a_m][a_k]      = cvt4(va0);
        *(float4*)&As[0][a_m + 64][a_k] = cvt4(va1);
        *(float4*)&Bst[0][b_n][b_k0]     = cvt4(make_float4(rb[0], rb[1], rb[2], rb[3]));
        *(float4*)&Bst[0][b_n][b_k0 + 4] = cvt4(make_float4(rb[4], rb[5], rb[6], rb[7]));
    }
    __syncthreads();

    const int ksteps = K / BKT;
    int cur = 0;
    for (int kt = 0; kt < ksteps; kt++) {
        float4 va0, va1;
        float rb[8];
        const bool has_next = (kt + 1 < ksteps);
        if (has_next) {
            int koff = (kt + 1) * BKT;
            va0 = make_float4(0.f,0.f,0.f,0.f); va1 = va0;
            if (gr0 < M) va0 = *(const float4*)(Ap0 + koff);
            if (gr1 < M) va1 = *(const float4*)(Ap1 + koff);
            const float* bp = Bp + (size_t)koff * N;
            #pragma unroll
            for (int i = 0; i < 8; i++) rb[i] = bp[(size_t)i * N];
        }

        // ---- compute on current buffer: 2 k8-steps ----
        #pragma unroll
        for (int kk = 0; kk < BKT; kk += 8) {
            uint32_t af[4][4], bf[4][2];
            #pragma unroll
            for (int mi = 0; mi < 4; mi++) {
                uint32_t ad = (uint32_t)__cvta_generic_to_shared(
                    &As[cur][wm * 64 + mi * 16 + a_frow][kk + a_fcol]);
                ldsm_x4(ad, af[mi][0], af[mi][1], af[mi][2], af[mi][3]);
            }
            #pragma unroll
            for (int ni = 0; ni < 4; ni++) {
                uint32_t ad = (uint32_t)__cvta_generic_to_shared(
                    &Bst[cur][wn * 32 + ni * 8 + b_frow][kk + b_fcol]);
                ldsm_x2(ad, bf[ni][0], bf[ni][1]);
            }
            #pragma unroll
            for (int mi = 0; mi < 4; mi++)
                #pragma unroll
                for (int ni = 0; ni < 4; ni++)
                    mma_tf32(acc[mi][ni], af[mi], bf[ni]);
        }

        if (has_next) {
            int nxt = cur ^ 1;
            *(float4*)&As[nxt][a_m][a_k]      = cvt4(va0);
            *(float4*)&As[nxt][a_m + 64][a_k] = cvt4(va1);
            *(float4*)&Bst[nxt][b_n][b_k0]     = cvt4(make_float4(rb[0], rb[1], rb[2], rb[3]));
            *(float4*)&Bst[nxt][b_n][b_k0 + 4] = cvt4(make_float4(rb[4], rb[5], rb[6], rb[7]));
            __syncthreads();
            cur = nxt;
        }
    }

    // ---- epilogue: c0=D[g][2tg] c1=D[g][2tg+1] c2=D[g+8][2tg] c3=D[g+8][2tg+1]
    #pragma unroll
    for (int ni = 0; ni < 4; ni++) {
        int c = col0 + wn * 32 + ni * 8 + 2 * tg;
        float2 bi = *(const float2*)(bias + c);
        #pragma unroll
        for (int mi = 0; mi < 4; mi++) {
            int r0 = row0 + wm * 64 + mi * 16 + g;
            int r1 = r0 + 8;
            if (r0 < M) {
                float2 o = make_float2(acc[mi][ni][0] + bi.x, acc[mi][ni][1] + bi.y);
                *(float2*)(Cm + (size_t)r0 * N + c) = o;
            }
            if (r1 < M) {
                float2 o = make_float2(acc[mi][ni][2] + bi.x, acc[mi][ni][3] + bi.y);
                *(float2*)(Cm + (size_t)r1 * N + c) = o;
            }
        }
    }
}

// ---------------- kernel 3: group LayerNorm(HD) + exact GELU + pos_embed ----------------
__global__ void ln_gelu_pos_kernel(const float* __restrict__ htlin,
                                   const float* __restrict__ lng,
                                   const float* __restrict__ lnb,
                                   const float* __restrict__ pos,
                                   float* __restrict__ xc)
{
    int gidx = blockIdx.x;                 // b*H*H + h*H + g
    int b = gidx / (Hv * Hv);
    int rem = gidx % (Hv * Hv);
    int h = rem / Hv, g = rem % Hv;
    int t = threadIdx.x;                   // 0..63

    float v = htlin[((size_t)(b * Hv + h)) * Cv + g * HDv + t];
    float s = v, s2 = v * v;
    #pragma unroll
    for (int off = 16; off; off >>= 1) {
        s  += __shfl_xor_sync(0xffffffffu, s,  off);
        s2 += __shfl_xor_sync(0xffffffffu, s2, off);
    }
    __shared__ float sh[4];
    int w = t >> 5, lane = t & 31;
    if (lane == 0) { sh[w] = s; sh[2 + w] = s2; }
    __syncthreads();
    float tot  = sh[0] + sh[1];
    float tot2 = sh[2] + sh[3];
    float mu  = tot * (1.f / HDv);
    float var = tot2 * (1.f / HDv) - mu * mu;
    float xn = (v - mu) * rsqrtf(var + 1e-5f) * lng[t] + lnb[t];
    float ge = 0.5f * xn * (1.f + erff(xn * 0.70710678118654752f));
    ge += pos[h * Cv + g * HDv + t];
    xc[((size_t)b * Tv + Nv + h) * Cv + g * HDv + t] = ge;
}

// ---------------- kernel 5: attention, one block per (b,h) ----------------
#define ATT_KT_STRIDE 256
#define ATT_P_STRIDE  224
#define ATT_SMEM_FLOATS (64*ATT_KT_STRIDE + Tv*HDv + 8*ATT_P_STRIDE + 8*HDv)

__global__ __launch_bounds__(256) void attn_kernel(const float* __restrict__ qkv,
                                                   float* __restrict__ attout)
{
    extern __shared__ float sm[];
    float* sKT = sm;                               // [64][256]
    float* sV  = sKT + 64 * ATT_KT_STRIDE;         // [209][64]
    float* sP  = sV + Tv * HDv;                    // [8][224]
    float* sQ  = sP + 8 * ATT_P_STRIDE;            // [8][64]

    int bh = blockIdx.x;
    int b = bh / Hv, h = bh % Hv;
    int tid = threadIdx.x;
    int w = tid >> 5, lane = tid & 31;
    const size_t base = (size_t)b * Tv * C3v + h * HDv;

    for (int i = tid; i < 64 * ATT_KT_STRIDE; i += 256) sKT[i] = 0.f;
    __syncthreads();
    for (int i = tid; i < Tv * HDv; i += 256) {
        int t = i >> 6, d = i & 63;
        sKT[d * ATT_KT_STRIDE + t] = qkv[base + (size_t)t * C3v + 768 + d];
        sV[i]                      = qkv[base + (size_t)t * C3v + 1536 + d];
    }
    __syncthreads();

    for (int r = w; r < Tv; r += 8) {
        sQ[w * 64 + lane]      = qkv[base + (size_t)r * C3v + lane];
        sQ[w * 64 + lane + 32] = qkv[base + (size_t)r * C3v + lane + 32];
        __syncwarp();

        float acc[8];
        #pragma unroll
        for (int i = 0; i < 8; i++) acc[i] = 0.f;

        #pragma unroll 8
        for (int d = 0; d < 64; d++) {
            float qd = sQ[w * 64 + d];
            float4 k0 = *(const float4*)&sKT[d * ATT_KT_STRIDE + lane * 4];
            float4 k1 = *(const float4*)&sKT[d * ATT_KT_STRIDE + 128 + lane * 4];
            acc[0] += qd * k0.x; acc[1] += qd * k0.y;
            acc[2] += qd * k0.z; acc[3] += qd * k0.w;
            acc[4] += qd * k1.x; acc[5] += qd * k1.y;
            acc[6] += qd * k1.z; acc[7] += qd * k1.w;
        }

        float m = -INFINITY;
        #pragma unroll
        for (int i = 0; i < 8; i++) {
            int j = (i < 4) ? (lane * 4 + i) : (128 + lane * 4 + (i - 4));
            acc[i] = (j < Tv) ? acc[i] * 0.125f : -INFINITY;
            m = fmaxf(m, acc[i]);
        }
        #pragma unroll
        for (int off = 16; off; off >>= 1)
            m = fmaxf(m, __shfl_xor_sync(0xffffffffu, m, off));
        float ssum = 0.f;
        #pragma unroll
        for (int i = 0; i < 8; i++) { acc[i] = __expf(acc[i] - m); ssum += acc[i]; }
        #pragma unroll
        for (int off = 16; off; off >>= 1)
            ssum += __shfl_xor_sync(0xffffffffu, ssum, off);
        float inv = 1.f / ssum;
        #pragma unroll
        for (int i = 0; i < 8; i++) {
            int j = (i < 4) ? (lane * 4 + i) : (128 + lane * 4 + (i - 4));
            if (j < Tv) sP[w * ATT_P_STRIDE + j] = acc[i] * inv;
        }
        __syncwarp();

        // O = P @ V with 2 independent accumulator chains (breaks serial dep)
        float o0a = 0.f, o1a = 0.f, o0b = 0.f, o1b = 0.f;
        #pragma unroll 4
        for (int j = 0; j < Tv - 1; j += 2) {
            float pj0 = sP[w * ATT_P_STRIDE + j];
            float pj1 = sP[w * ATT_P_STRIDE + j + 1];
            float2 v0 = *(const float2*)&sV[j * 64 + lane * 2];
            float2 v1 = *(const float2*)&sV[(j + 1) * 64 + lane * 2];
            o0a += pj0 * v0.x; o1a += pj0 * v0.y;
            o0b += pj1 * v1.x; o1b += pj1 * v1.y;
        }
        {   // tail j = Tv-1 (Tv odd)
            float pj = sP[w * ATT_P_STRIDE + (Tv - 1)];
            float2 vv = *(const float2*)&sV[(Tv - 1) * 64 + lane * 2];
            o0a += pj * vv.x; o1a += pj * vv.y;
        }
        float* op = attout + ((size_t)b * Tv + r) * Cv + h * HDv + lane * 2;
        op[0] = o0a + o0b; op[1] = o1a + o1b;
        __syncwarp();
    }
}

// ---------------- kernel 7: cls merge + copy ----------------
__global__ void final_kernel(const float* __restrict__ pr, float* __restrict__ out) {
    int idx = blockIdx.x * blockDim.x + threadIdx.x;
    const int total = Bv * Nv * Cv;
    if (idx >= total) return;
    int c = idx % Cv;
    int t = (idx / Cv) % Nv;
    int b = idx / (Nv * Cv);
    float v = pr[((size_t)b * Tv + t) * Cv + c];
    if (t == 0) {
        float s = 0.f;
        #pragma unroll
        for (int hh = 0; hh < Hv; hh++)
            s += pr[((size_t)b * Tv + Nv + hh) * Cv + c];
        v += s * (1.f / Hv);
    }
    out[idx] = v;
}

// ---------------- launcher ----------------
extern "C" void kernel_launch(void* const* d_in, const int* in_sizes, int n_in,
                              void* d_out, int out_size)
{
    const float* x      = (const float*)d_in[0];
    const float* qkv_w  = (const float*)d_in[1];
    const float* qkv_b  = (const float*)d_in[2];
    const float* proj_w = (const float*)d_in[3];
    const float* proj_b = (const float*)d_in[4];
    const float* ht_w   = (const float*)d_in[5];
    const float* ht_b   = (const float*)d_in[6];
    const float* ln_g   = (const float*)d_in[7];
    const float* ln_b   = (const float*)d_in[8];
    const float* pos    = (const float*)d_in[9];
    float* out          = (float*)d_out;

    float *p_htmean, *p_htlin, *p_xc, *p_qkv, *p_att, *p_proj;
    cudaGetSymbolAddress((void**)&p_htmean, g_htmean);
    cudaGetSymbolAddress((void**)&p_htlin,  g_htlin);
    cudaGetSymbolAddress((void**)&p_xc,     g_xc);
    cudaGetSymbolAddress((void**)&p_qkv,    g_qkv);
    cudaGetSymbolAddress((void**)&p_att,    g_att);
    cudaGetSymbolAddress((void**)&p_proj,   g_proj);

    // copy x into the first N rows of each batch of xc
    cudaMemcpy2DAsync(p_xc, (size_t)Tv * Cv * sizeof(float),
                      x,    (size_t)Nv * Cv * sizeof(float),
                      (size_t)Nv * Cv * sizeof(float), Bv,
                      cudaMemcpyDeviceToDevice, 0);

    // 1) head-token mean over N
    {
        int total = Bv * Cv;
        htmean_kernel<<<(total + 255) / 256, 256>>>(x, p_htmean);
    }

    // 2) ht linear: (B*H, HD) @ (HD, C) + ht_b
    {
        dim3 grid(Cv / BN, (Bv * Hv + BM - 1) / BM);
        tgemm_bias<<<grid, 256>>>(p_htmean, ht_w, ht_b, p_htlin, Bv * Hv, Cv, HDv);
    }

    // 3) LN + GELU + pos_embed -> xc rows [N, T)
    ln_gelu_pos_kernel<<<Bv * Hv * Hv, 64>>>(p_htlin, ln_g, ln_b, pos, p_xc);

    // 4) QKV GEMM: (B*T, C) @ (C, 3C) + qkv_b
    {
        dim3 grid(C3v / BN, (Bv * Tv + BM - 1) / BM);
        tgemm_bias<<<grid, 256>>>(p_xc, qkv_w, qkv_b, p_qkv, Bv * Tv, C3v, Cv);
    }

    // 5) attention per (b, h)
    {
        size_t smem = ATT_SMEM_FLOATS * sizeof(float);
        cudaFuncSetAttribute(attn_kernel, cudaFuncAttributeMaxDynamicSharedMemorySize, (int)smem);
        attn_kernel<<<Bv * Hv, 256, smem>>>(p_qkv, p_att);
    }

    // 6) proj GEMM: (B*T, C) @ (C, C) + proj_b
    {
        dim3 grid(Cv / BN, (Bv * Tv + BM - 1) / BM);
        tgemm_bias<<<grid, 256>>>(p_att, proj_w, proj_b, p_proj, Bv * Tv, Cv, Cv);
    }

    // 7) cls merge + output copy
    {
        int total = Bv * Nv * Cv;
        final_kernel<<<(total + 255) / 256, 256>>>(p_proj, out);
    }
}